// round 3
// baseline (speedup 1.0000x reference)
#include <cuda_runtime.h>
#include <cuda_fp16.h>
#include <cstdint>

// ============================================================================
// out[8192,1536] = x[8192,3072] @ (mask.T * w)[3072,1536] + b
// Base-target-safe path: mma.sync m16n8k16 fp16 (HMMA), cp.async pipeline.
// (tcgen05 is unavailable: harness compiles PTX at compute_103, not 103a.)
// ============================================================================

static constexpr int MDIM = 8192;
static constexpr int NDIM = 1536;
static constexpr int KDIM = 3072;

static constexpr int TM = 128;
static constexpr int TN = 128;
static constexpr int TK = 64;               // halves per k-tile = 128 B/row
static constexpr int STAGES = 4;
static constexpr int KITERS = KDIM / TK;    // 48
static constexpr int TILES_N = NDIM / TN;   // 12
static constexpr int TILES_M = MDIM / TM;   // 64

static constexpr int A_BYTES = TM * TK * 2;       // 16384
static constexpr int B_BYTES = TN * TK * 2;       // 16384
static constexpr int STAGE_BYTES = A_BYTES + B_BYTES;  // 32768
static constexpr int SMEM_TOTAL = STAGES * STAGE_BYTES; // 131072

// fp16 staging buffers (device globals: no runtime allocation)
__device__ __half g_xh[(size_t)MDIM * KDIM];   // 50.3 MB
__device__ __half g_Bh[(size_t)NDIM * KDIM];   // 9.4 MB, [n][k]

// ---------------------------------------------------------------------------
// PTX helpers
// ---------------------------------------------------------------------------
__device__ __forceinline__ uint32_t smem_u32(const void* p) {
    uint32_t a;
    asm("{ .reg .u64 t; cvta.to.shared.u64 t, %1; cvt.u32.u64 %0, t; }" : "=r"(a) : "l"(p));
    return a;
}

#define CP_ASYNC16(dst, src) \
    asm volatile("cp.async.cg.shared.global [%0], [%1], 16;" :: "r"(dst), "l"(src) : "memory")
#define CP_COMMIT() asm volatile("cp.async.commit_group;" ::: "memory")
#define CP_WAIT2()  asm volatile("cp.async.wait_group 2;" ::: "memory")

#define LDSM_X4(r0, r1, r2, r3, addr) \
    asm volatile("ldmatrix.sync.aligned.m8n8.x4.shared.b16 {%0,%1,%2,%3}, [%4];" \
                 : "=r"(r0), "=r"(r1), "=r"(r2), "=r"(r3) : "r"(addr))

#define MMA16816(d, a0, a1, a2, a3, b0, b1) \
    asm volatile("mma.sync.aligned.m16n8k16.row.col.f32.f16.f16.f32 " \
                 "{%0,%1,%2,%3}, {%4,%5,%6,%7}, {%8,%9}, {%0,%1,%2,%3};" \
                 : "+f"((d)[0]), "+f"((d)[1]), "+f"((d)[2]), "+f"((d)[3]) \
                 : "r"(a0), "r"(a1), "r"(a2), "r"(a3), "r"(b0), "r"(b1))

// ---------------------------------------------------------------------------
// Kernel 1: convert x (fp32) -> g_xh (fp16), 8 elements / thread
// ---------------------------------------------------------------------------
__global__ void __launch_bounds__(256) conv_x_kernel(const float* __restrict__ x) {
    size_t i = (size_t)blockIdx.x * 256 + threadIdx.x;
    const float4* xv = reinterpret_cast<const float4*>(x);
    float4 a = xv[2 * i];
    float4 c = xv[2 * i + 1];
    __half2 h[4];
    h[0] = __floats2half2_rn(a.x, a.y);
    h[1] = __floats2half2_rn(a.z, a.w);
    h[2] = __floats2half2_rn(c.x, c.y);
    h[3] = __floats2half2_rn(c.z, c.w);
    uint4 u;
    u.x = *reinterpret_cast<uint32_t*>(&h[0]);
    u.y = *reinterpret_cast<uint32_t*>(&h[1]);
    u.z = *reinterpret_cast<uint32_t*>(&h[2]);
    u.w = *reinterpret_cast<uint32_t*>(&h[3]);
    reinterpret_cast<uint4*>(g_xh)[i] = u;
}

// ---------------------------------------------------------------------------
// Kernel 2: g_Bh[n][k] = fp16(mask[n][k] * w[k][n])  (smem transpose of w)
// ---------------------------------------------------------------------------
__global__ void __launch_bounds__(256) prep_B_kernel(const float* __restrict__ w,
                                                     const float* __restrict__ mask) {
    __shared__ float ws[32][33];
    int k0 = blockIdx.x * 32;
    int n0 = blockIdx.y * 32;
    int tx = threadIdx.x;   // 0..31
    int ty = threadIdx.y;   // 0..7
#pragma unroll
    for (int i = 0; i < 32; i += 8)
        ws[ty + i][tx] = w[(size_t)(k0 + ty + i) * NDIM + (n0 + tx)];
    __syncthreads();
#pragma unroll
    for (int i = 0; i < 32; i += 8) {
        int n = n0 + ty + i;
        int k = k0 + tx;
        size_t idx = (size_t)n * KDIM + k;
        g_Bh[idx] = __float2half(mask[idx] * ws[tx][ty + i]);
    }
}

// ---------------------------------------------------------------------------
// Kernel 3: GEMM 128x128 CTA tile, 8 warps (4M x 2N), mma.sync fp16
// ---------------------------------------------------------------------------
__device__ __forceinline__ void load_stage(uint32_t sa, int m0, int n0, int kc, int tid) {
    const __half* xa = g_xh + (size_t)m0 * KDIM + kc * TK;
#pragma unroll
    for (int i = 0; i < 4; ++i) {
        int c = tid + i * 256;
        int row = c >> 3, q = c & 7;
        uint32_t dst = sa + row * 128 + ((q ^ (row & 7)) << 4);
        CP_ASYNC16(dst, xa + (size_t)row * KDIM + q * 8);
    }
    const __half* ba = g_Bh + (size_t)n0 * KDIM + kc * TK;
#pragma unroll
    for (int i = 0; i < 4; ++i) {
        int c = tid + i * 256;
        int row = c >> 3, q = c & 7;
        uint32_t dst = sa + A_BYTES + row * 128 + ((q ^ (row & 7)) << 4);
        CP_ASYNC16(dst, ba + (size_t)row * KDIM + q * 8);
    }
}

__global__ void __launch_bounds__(256, 1) gemm_f16_kernel(const float* __restrict__ bias,
                                                          float* __restrict__ out) {
    extern __shared__ char smem[];
    const uint32_t sbase = smem_u32(smem);
    const int tid = threadIdx.x;
    const int wid = tid >> 5;
    const int lane = tid & 31;
    const int mw = wid >> 1;   // 0..3   (rows mw*32 .. +31)
    const int nw = wid & 1;    // 0..1   (cols nw*64 .. +63)

    const int tn = blockIdx.x % TILES_N;
    const int tm = blockIdx.x / TILES_N;
    const int m0 = tm * TM;
    const int n0 = tn * TN;

    float acc[2][8][4];
#pragma unroll
    for (int i = 0; i < 2; ++i)
#pragma unroll
        for (int j = 0; j < 8; ++j)
#pragma unroll
            for (int q = 0; q < 4; ++q) acc[i][j][q] = 0.0f;

    // Prologue: stages 0..2
#pragma unroll
    for (int s = 0; s < STAGES - 1; ++s) {
        load_stage(sbase + s * STAGE_BYTES, m0, n0, s, tid);
        CP_COMMIT();
    }

    // Precompute per-lane ldmatrix row/chunk components
    const int a_rowsel = lane & 15;          // + mt*16 + mw*32
    const int a_chunksel = lane >> 4;        // + ks*2
    const int b_rowsel = ((lane >> 4) << 3) + (lane & 7);  // + nt2*16 + nw*64
    const int b_chunksel = (lane >> 3) & 1;  // + ks*2

    for (int j = 0; j < KITERS; ++j) {
        CP_WAIT2();          // stage j complete (pending j..j+2 before wait)
        __syncthreads();     // CTA-wide visibility; all warps past compute j-1

        const int jn = j + STAGES - 1;
        if (jn < KITERS)
            load_stage(sbase + (jn & (STAGES - 1)) * STAGE_BYTES, m0, n0, jn, tid);
        CP_COMMIT();

        const uint32_t aBase = sbase + (j & (STAGES - 1)) * STAGE_BYTES;
        const uint32_t bBase = aBase + A_BYTES;

#pragma unroll
        for (int ks = 0; ks < 4; ++ks) {
            uint32_t af[2][4];
#pragma unroll
            for (int mt = 0; mt < 2; ++mt) {
                int row = mw * 32 + mt * 16 + a_rowsel;
                int chunk = ks * 2 + a_chunksel;
                uint32_t addr = aBase + row * 128 + ((chunk ^ (row & 7)) << 4);
                LDSM_X4(af[mt][0], af[mt][1], af[mt][2], af[mt][3], addr);
            }
            uint32_t bf[4][4];
#pragma unroll
            for (int nt2 = 0; nt2 < 4; ++nt2) {
                int row = nw * 64 + nt2 * 16 + b_rowsel;
                int chunk = ks * 2 + b_chunksel;
                uint32_t addr = bBase + row * 128 + ((chunk ^ (row & 7)) << 4);
                LDSM_X4(bf[nt2][0], bf[nt2][1], bf[nt2][2], bf[nt2][3], addr);
            }
#pragma unroll
            for (int mt = 0; mt < 2; ++mt)
#pragma unroll
                for (int nt = 0; nt < 8; ++nt) {
                    const uint32_t b0 = bf[nt >> 1][(nt & 1) * 2 + 0];
                    const uint32_t b1 = bf[nt >> 1][(nt & 1) * 2 + 1];
                    MMA16816(acc[mt][nt], af[mt][0], af[mt][1], af[mt][2], af[mt][3], b0, b1);
                }
        }
    }

    // Epilogue: direct global stores + bias
    const int grp = lane >> 2, tig = lane & 3;
#pragma unroll
    for (int mt = 0; mt < 2; ++mt) {
        const int row0 = m0 + mw * 32 + mt * 16 + grp;
#pragma unroll
        for (int nt = 0; nt < 8; ++nt) {
            const int col = n0 + nw * 64 + nt * 8 + tig * 2;
            const float2 bb = *reinterpret_cast<const float2*>(bias + col);
            float2 v0, v1;
            v0.x = acc[mt][nt][0] + bb.x;
            v0.y = acc[mt][nt][1] + bb.y;
            v1.x = acc[mt][nt][2] + bb.x;
            v1.y = acc[mt][nt][3] + bb.y;
            *reinterpret_cast<float2*>(out + (size_t)row0 * NDIM + col) = v0;
            *reinterpret_cast<float2*>(out + (size_t)(row0 + 8) * NDIM + col) = v1;
        }
    }
}

// ---------------------------------------------------------------------------
// Launch
// ---------------------------------------------------------------------------
extern "C" void kernel_launch(void* const* d_in, const int* in_sizes, int n_in,
                              void* d_out, int out_size) {
    const float* x    = (const float*)d_in[0];   // [8192, 3072]
    const float* w    = (const float*)d_in[1];   // [3072, 1536]
    const float* b    = (const float*)d_in[2];   // [1536]
    const float* mask = (const float*)d_in[3];   // [1536, 3072]
    float* out = (float*)d_out;                  // [8192, 1536]

    // 1) x -> fp16
    conv_x_kernel<<<(MDIM * KDIM) / (256 * 8), 256>>>(x);

    // 2) Bh = fp16(mask * w^T)
    prep_B_kernel<<<dim3(KDIM / 32, NDIM / 32), dim3(32, 8)>>>(w, mask);

    // 3) fp16 HMMA GEMM
    cudaFuncSetAttribute(gemm_f16_kernel, cudaFuncAttributeMaxDynamicSharedMemorySize,
                         SMEM_TOTAL);
    gemm_f16_kernel<<<TILES_M * TILES_N, 256, SMEM_TOTAL>>>(b, out);
}

// round 4
// speedup vs baseline: 1.6986x; 1.6986x over previous
#include <cuda_runtime.h>
#include <cuda_fp16.h>
#include <cstdint>

// ============================================================================
// out[8192,1536] = x[8192,3072] @ (mask.T * w)[3072,1536] + b
// mma.sync m16n8k16 fp16 (HMMA), cp.async 4-stage pipeline.
// R3: CTA tile 128x256, 512 threads (16 warps = 4/SMSP), warp tile 64x32.
// ============================================================================

static constexpr int MDIM = 8192;
static constexpr int NDIM = 1536;
static constexpr int KDIM = 3072;

static constexpr int TM = 128;
static constexpr int TN = 256;
static constexpr int TK = 64;               // halves per k-tile = 128 B/row
static constexpr int STAGES = 4;
static constexpr int KITERS = KDIM / TK;    // 48
static constexpr int TILES_N = NDIM / TN;   // 6
static constexpr int TILES_M = MDIM / TM;   // 64

static constexpr int A_BYTES = TM * TK * 2;             // 16384
static constexpr int B_BYTES = TN * TK * 2;             // 32768
static constexpr int STAGE_BYTES = A_BYTES + B_BYTES;   // 49152
static constexpr int SMEM_TOTAL = STAGES * STAGE_BYTES; // 196608

// fp16 staging buffers (device globals: no runtime allocation)
__device__ __half g_xh[(size_t)MDIM * KDIM];   // 50.3 MB
__device__ __half g_Bh[(size_t)NDIM * KDIM];   // 9.4 MB, [n][k]

// ---------------------------------------------------------------------------
// PTX helpers
// ---------------------------------------------------------------------------
__device__ __forceinline__ uint32_t smem_u32(const void* p) {
    uint32_t a;
    asm("{ .reg .u64 t; cvta.to.shared.u64 t, %1; cvt.u32.u64 %0, t; }" : "=r"(a) : "l"(p));
    return a;
}

#define CP_ASYNC16(dst, src) \
    asm volatile("cp.async.cg.shared.global [%0], [%1], 16;" :: "r"(dst), "l"(src) : "memory")
#define CP_COMMIT() asm volatile("cp.async.commit_group;" ::: "memory")
#define CP_WAIT2()  asm volatile("cp.async.wait_group 2;" ::: "memory")

#define LDSM_X4(r0, r1, r2, r3, addr) \
    asm volatile("ldmatrix.sync.aligned.m8n8.x4.shared.b16 {%0,%1,%2,%3}, [%4];" \
                 : "=r"(r0), "=r"(r1), "=r"(r2), "=r"(r3) : "r"(addr))

#define MMA16816(d, a0, a1, a2, a3, b0, b1) \
    asm volatile("mma.sync.aligned.m16n8k16.row.col.f32.f16.f16.f32 " \
                 "{%0,%1,%2,%3}, {%4,%5,%6,%7}, {%8,%9}, {%0,%1,%2,%3};" \
                 : "+f"((d)[0]), "+f"((d)[1]), "+f"((d)[2]), "+f"((d)[3]) \
                 : "r"(a0), "r"(a1), "r"(a2), "r"(a3), "r"(b0), "r"(b1))

// ---------------------------------------------------------------------------
// Kernel 1: convert x (fp32) -> g_xh (fp16), 8 elements / thread
// ---------------------------------------------------------------------------
__global__ void __launch_bounds__(256) conv_x_kernel(const float* __restrict__ x) {
    size_t i = (size_t)blockIdx.x * 256 + threadIdx.x;
    const float4* xv = reinterpret_cast<const float4*>(x);
    float4 a = xv[2 * i];
    float4 c = xv[2 * i + 1];
    __half2 h[4];
    h[0] = __floats2half2_rn(a.x, a.y);
    h[1] = __floats2half2_rn(a.z, a.w);
    h[2] = __floats2half2_rn(c.x, c.y);
    h[3] = __floats2half2_rn(c.z, c.w);
    uint4 u;
    u.x = *reinterpret_cast<uint32_t*>(&h[0]);
    u.y = *reinterpret_cast<uint32_t*>(&h[1]);
    u.z = *reinterpret_cast<uint32_t*>(&h[2]);
    u.w = *reinterpret_cast<uint32_t*>(&h[3]);
    reinterpret_cast<uint4*>(g_xh)[i] = u;
}

// ---------------------------------------------------------------------------
// Kernel 2: g_Bh[n][k] = fp16(mask[n][k] * w[k][n])  (smem transpose of w)
// ---------------------------------------------------------------------------
__global__ void __launch_bounds__(256) prep_B_kernel(const float* __restrict__ w,
                                                     const float* __restrict__ mask) {
    __shared__ float ws[32][33];
    int k0 = blockIdx.x * 32;
    int n0 = blockIdx.y * 32;
    int tx = threadIdx.x;   // 0..31
    int ty = threadIdx.y;   // 0..7
#pragma unroll
    for (int i = 0; i < 32; i += 8)
        ws[ty + i][tx] = w[(size_t)(k0 + ty + i) * NDIM + (n0 + tx)];
    __syncthreads();
#pragma unroll
    for (int i = 0; i < 32; i += 8) {
        int n = n0 + ty + i;
        int k = k0 + tx;
        size_t idx = (size_t)n * KDIM + k;
        g_Bh[idx] = __float2half(mask[idx] * ws[tx][ty + i]);
    }
}

// ---------------------------------------------------------------------------
// Kernel 3: GEMM 128x256 CTA tile, 16 warps (2M x 8N), warp tile 64x32
// ---------------------------------------------------------------------------
__device__ __forceinline__ void load_stage(uint32_t sa, int m0, int n0, int kc, int tid) {
    // A: 128 rows x 64 halves = 1024 x 16B chunks; 512 threads -> 2 each
    const __half* xa = g_xh + (size_t)m0 * KDIM + kc * TK;
#pragma unroll
    for (int i = 0; i < 2; ++i) {
        int c = tid + i * 512;
        int row = c >> 3, q = c & 7;
        uint32_t dst = sa + row * 128 + ((q ^ (row & 7)) << 4);
        CP_ASYNC16(dst, xa + (size_t)row * KDIM + q * 8);
    }
    // B: 256 rows x 64 halves = 2048 x 16B chunks; 512 threads -> 4 each
    const __half* ba = g_Bh + (size_t)n0 * KDIM + kc * TK;
#pragma unroll
    for (int i = 0; i < 4; ++i) {
        int c = tid + i * 512;
        int row = c >> 3, q = c & 7;
        uint32_t dst = sa + A_BYTES + row * 128 + ((q ^ (row & 7)) << 4);
        CP_ASYNC16(dst, ba + (size_t)row * KDIM + q * 8);
    }
}

__global__ void __launch_bounds__(512, 1) gemm_f16_kernel(const float* __restrict__ bias,
                                                          float* __restrict__ out) {
    extern __shared__ char smem[];
    const uint32_t sbase = smem_u32(smem);
    const int tid = threadIdx.x;
    const int wid = tid >> 5;
    const int lane = tid & 31;
    const int mw = wid & 1;    // 0..1  -> rows mw*64 .. +63
    const int nwn = wid >> 1;  // 0..7  -> cols nwn*32 .. +31

    const int tn = blockIdx.x % TILES_N;
    const int tm = blockIdx.x / TILES_N;
    const int m0 = tm * TM;
    const int n0 = tn * TN;

    float acc[4][4][4];
#pragma unroll
    for (int i = 0; i < 4; ++i)
#pragma unroll
        for (int j = 0; j < 4; ++j)
#pragma unroll
            for (int q = 0; q < 4; ++q) acc[i][j][q] = 0.0f;

    // Prologue: stages 0..2
#pragma unroll
    for (int s = 0; s < STAGES - 1; ++s) {
        load_stage(sbase + s * STAGE_BYTES, m0, n0, s, tid);
        CP_COMMIT();
    }

    // Per-lane ldmatrix row/chunk selectors
    const int a_rowsel = lane & 15;                        // + mt*16 + mw*64
    const int a_chunksel = lane >> 4;                      // + ks*2
    const int b_rowsel = ((lane >> 4) << 3) + (lane & 7);  // + g*16 + nwn*32
    const int b_chunksel = (lane >> 3) & 1;                // + ks*2

    for (int j = 0; j < KITERS; ++j) {
        CP_WAIT2();          // stage j complete
        __syncthreads();     // CTA-wide visibility of stage j

        const int jn = j + STAGES - 1;
        if (jn < KITERS)
            load_stage(sbase + (jn & (STAGES - 1)) * STAGE_BYTES, m0, n0, jn, tid);
        CP_COMMIT();

        const uint32_t aBase = sbase + (j & (STAGES - 1)) * STAGE_BYTES;
        const uint32_t bBase = aBase + A_BYTES;

#pragma unroll
        for (int ks = 0; ks < 4; ++ks) {
            uint32_t af[4][4];
#pragma unroll
            for (int mt = 0; mt < 4; ++mt) {
                int row = mw * 64 + mt * 16 + a_rowsel;
                int chunk = ks * 2 + a_chunksel;
                uint32_t addr = aBase + row * 128 + ((chunk ^ (row & 7)) << 4);
                LDSM_X4(af[mt][0], af[mt][1], af[mt][2], af[mt][3], addr);
            }
            uint32_t bf[2][4];
#pragma unroll
            for (int g = 0; g < 2; ++g) {
                int row = nwn * 32 + g * 16 + b_rowsel;
                int chunk = ks * 2 + b_chunksel;
                uint32_t addr = bBase + row * 128 + ((chunk ^ (row & 7)) << 4);
                LDSM_X4(bf[g][0], bf[g][1], bf[g][2], bf[g][3], addr);
            }
#pragma unroll
            for (int mt = 0; mt < 4; ++mt)
#pragma unroll
                for (int nt = 0; nt < 4; ++nt) {
                    const uint32_t b0 = bf[nt >> 1][(nt & 1) * 2 + 0];
                    const uint32_t b1 = bf[nt >> 1][(nt & 1) * 2 + 1];
                    MMA16816(acc[mt][nt], af[mt][0], af[mt][1], af[mt][2], af[mt][3], b0, b1);
                }
        }
    }

    // Epilogue: direct global stores + bias
    const int grp = lane >> 2, tig = lane & 3;
#pragma unroll
    for (int mt = 0; mt < 4; ++mt) {
        const int row0 = m0 + mw * 64 + mt * 16 + grp;
#pragma unroll
        for (int nt = 0; nt < 4; ++nt) {
            const int col = n0 + nwn * 32 + nt * 8 + tig * 2;
            const float2 bb = *reinterpret_cast<const float2*>(bias + col);
            float2 v0, v1;
            v0.x = acc[mt][nt][0] + bb.x;
            v0.y = acc[mt][nt][1] + bb.y;
            v1.x = acc[mt][nt][2] + bb.x;
            v1.y = acc[mt][nt][3] + bb.y;
            *reinterpret_cast<float2*>(out + (size_t)row0 * NDIM + col) = v0;
            *reinterpret_cast<float2*>(out + (size_t)(row0 + 8) * NDIM + col) = v1;
        }
    }
}

// ---------------------------------------------------------------------------
// Launch
// ---------------------------------------------------------------------------
extern "C" void kernel_launch(void* const* d_in, const int* in_sizes, int n_in,
                              void* d_out, int out_size) {
    const float* x    = (const float*)d_in[0];   // [8192, 3072]
    const float* w    = (const float*)d_in[1];   // [3072, 1536]
    const float* b    = (const float*)d_in[2];   // [1536]
    const float* mask = (const float*)d_in[3];   // [1536, 3072]
    float* out = (float*)d_out;                  // [8192, 1536]

    // 1) x -> fp16
    conv_x_kernel<<<(MDIM * KDIM) / (256 * 8), 256>>>(x);

    // 2) Bh = fp16(mask * w^T)
    prep_B_kernel<<<dim3(KDIM / 32, NDIM / 32), dim3(32, 8)>>>(w, mask);

    // 3) fp16 HMMA GEMM
    cudaFuncSetAttribute(gemm_f16_kernel, cudaFuncAttributeMaxDynamicSharedMemorySize,
                         SMEM_TOTAL);
    gemm_f16_kernel<<<TILES_M * TILES_N, 512, SMEM_TOTAL>>>(b, out);
}

// round 5
// speedup vs baseline: 1.7569x; 1.0343x over previous
#include <cuda_runtime.h>
#include <cuda_fp16.h>
#include <cstdint>

// ============================================================================
// out[8192,1536] = x[8192,3072] @ (mask.T * w)[3072,1536] + b
// mma.sync m16n8k16 fp16 (HMMA), cp.async 3-stage pipeline.
// R5: CTA tile 128x128, 256 threads, 2 CTAs/SM (cross-CTA bubble filling).
// ============================================================================

static constexpr int MDIM = 8192;
static constexpr int NDIM = 1536;
static constexpr int KDIM = 3072;

static constexpr int TM = 128;
static constexpr int TN = 128;
static constexpr int TK = 64;               // halves per k-tile = 128 B/row
static constexpr int STAGES = 3;
static constexpr int KITERS = KDIM / TK;    // 48
static constexpr int TILES_N = NDIM / TN;   // 12
static constexpr int TILES_M = MDIM / TM;   // 64

static constexpr int A_BYTES = TM * TK * 2;             // 16384
static constexpr int B_BYTES = TN * TK * 2;             // 16384
static constexpr int STAGE_BYTES = A_BYTES + B_BYTES;   // 32768
static constexpr int SMEM_TOTAL = STAGES * STAGE_BYTES; // 98304 -> 2 CTAs/SM

// fp16 staging buffers (device globals: no runtime allocation)
__device__ __half g_xh[(size_t)MDIM * KDIM];   // 50.3 MB
__device__ __half g_Bh[(size_t)NDIM * KDIM];   // 9.4 MB, [n][k]

// ---------------------------------------------------------------------------
// PTX helpers
// ---------------------------------------------------------------------------
__device__ __forceinline__ uint32_t smem_u32(const void* p) {
    uint32_t a;
    asm("{ .reg .u64 t; cvta.to.shared.u64 t, %1; cvt.u32.u64 %0, t; }" : "=r"(a) : "l"(p));
    return a;
}

#define CP_ASYNC16(dst, src) \
    asm volatile("cp.async.cg.shared.global [%0], [%1], 16;" :: "r"(dst), "l"(src) : "memory")
#define CP_COMMIT() asm volatile("cp.async.commit_group;" ::: "memory")
#define CP_WAIT1()  asm volatile("cp.async.wait_group 1;" ::: "memory")

#define LDSM_X4(r0, r1, r2, r3, addr) \
    asm volatile("ldmatrix.sync.aligned.m8n8.x4.shared.b16 {%0,%1,%2,%3}, [%4];" \
                 : "=r"(r0), "=r"(r1), "=r"(r2), "=r"(r3) : "r"(addr))

#define MMA16816(d, a0, a1, a2, a3, b0, b1) \
    asm volatile("mma.sync.aligned.m16n8k16.row.col.f32.f16.f16.f32 " \
                 "{%0,%1,%2,%3}, {%4,%5,%6,%7}, {%8,%9}, {%0,%1,%2,%3};" \
                 : "+f"((d)[0]), "+f"((d)[1]), "+f"((d)[2]), "+f"((d)[3]) \
                 : "r"(a0), "r"(a1), "r"(a2), "r"(a3), "r"(b0), "r"(b1))

// ---------------------------------------------------------------------------
// Kernel 1: convert x (fp32) -> g_xh (fp16), 8 elements / thread
// ---------------------------------------------------------------------------
__global__ void __launch_bounds__(256) conv_x_kernel(const float* __restrict__ x) {
    size_t i = (size_t)blockIdx.x * 256 + threadIdx.x;
    const float4* xv = reinterpret_cast<const float4*>(x);
    float4 a = xv[2 * i];
    float4 c = xv[2 * i + 1];
    __half2 h[4];
    h[0] = __floats2half2_rn(a.x, a.y);
    h[1] = __floats2half2_rn(a.z, a.w);
    h[2] = __floats2half2_rn(c.x, c.y);
    h[3] = __floats2half2_rn(c.z, c.w);
    uint4 u;
    u.x = *reinterpret_cast<uint32_t*>(&h[0]);
    u.y = *reinterpret_cast<uint32_t*>(&h[1]);
    u.z = *reinterpret_cast<uint32_t*>(&h[2]);
    u.w = *reinterpret_cast<uint32_t*>(&h[3]);
    reinterpret_cast<uint4*>(g_xh)[i] = u;
}

// ---------------------------------------------------------------------------
// Kernel 2: g_Bh[n][k] = fp16(mask[n][k] * w[k][n])  (smem transpose of w)
// ---------------------------------------------------------------------------
__global__ void __launch_bounds__(256) prep_B_kernel(const float* __restrict__ w,
                                                     const float* __restrict__ mask) {
    __shared__ float ws[32][33];
    int k0 = blockIdx.x * 32;
    int n0 = blockIdx.y * 32;
    int tx = threadIdx.x;   // 0..31
    int ty = threadIdx.y;   // 0..7
#pragma unroll
    for (int i = 0; i < 32; i += 8)
        ws[ty + i][tx] = w[(size_t)(k0 + ty + i) * NDIM + (n0 + tx)];
    __syncthreads();
#pragma unroll
    for (int i = 0; i < 32; i += 8) {
        int n = n0 + ty + i;
        int k = k0 + tx;
        size_t idx = (size_t)n * KDIM + k;
        g_Bh[idx] = __float2half(mask[idx] * ws[tx][ty + i]);
    }
}

// ---------------------------------------------------------------------------
// Kernel 3: GEMM 128x128 CTA tile, 8 warps (4M x 2N), warp tile 32x64
// ---------------------------------------------------------------------------
__device__ __forceinline__ void load_stage(uint32_t sa, int m0, int n0, int kc, int tid) {
    // A: 128 rows x 64 halves = 1024 x 16B chunks; 256 threads -> 4 each
    const __half* xa = g_xh + (size_t)m0 * KDIM + kc * TK;
#pragma unroll
    for (int i = 0; i < 4; ++i) {
        int c = tid + i * 256;
        int row = c >> 3, q = c & 7;
        uint32_t dst = sa + row * 128 + ((q ^ (row & 7)) << 4);
        CP_ASYNC16(dst, xa + (size_t)row * KDIM + q * 8);
    }
    // B: 128 rows x 64 halves = 1024 x 16B chunks; 256 threads -> 4 each
    const __half* ba = g_Bh + (size_t)n0 * KDIM + kc * TK;
#pragma unroll
    for (int i = 0; i < 4; ++i) {
        int c = tid + i * 256;
        int row = c >> 3, q = c & 7;
        uint32_t dst = sa + A_BYTES + row * 128 + ((q ^ (row & 7)) << 4);
        CP_ASYNC16(dst, ba + (size_t)row * KDIM + q * 8);
    }
}

__global__ void __launch_bounds__(256, 2) gemm_f16_kernel(const float* __restrict__ bias,
                                                          float* __restrict__ out) {
    extern __shared__ char smem[];
    const uint32_t sbase = smem_u32(smem);
    const int tid = threadIdx.x;
    const int wid = tid >> 5;
    const int lane = tid & 31;
    const int mw = wid >> 1;   // 0..3   (rows mw*32 .. +31)
    const int nw = wid & 1;    // 0..1   (cols nw*64 .. +63)

    const int tn = blockIdx.x % TILES_N;
    const int tm = blockIdx.x / TILES_N;
    const int m0 = tm * TM;
    const int n0 = tn * TN;

    float acc[2][8][4];
#pragma unroll
    for (int i = 0; i < 2; ++i)
#pragma unroll
        for (int j = 0; j < 8; ++j)
#pragma unroll
            for (int q = 0; q < 4; ++q) acc[i][j][q] = 0.0f;

    // Prologue: stages 0..1
#pragma unroll
    for (int s = 0; s < STAGES - 1; ++s) {
        load_stage(sbase + s * STAGE_BYTES, m0, n0, s, tid);
        CP_COMMIT();
    }

    // Per-lane ldmatrix row/chunk selectors
    const int a_rowsel = lane & 15;                        // + mt*16 + mw*32
    const int a_chunksel = lane >> 4;                      // + ks*2
    const int b_rowsel = ((lane >> 4) << 3) + (lane & 7);  // + g*16 + nw*64
    const int b_chunksel = (lane >> 3) & 1;                // + ks*2

    int stage = 0;
    for (int j = 0; j < KITERS; ++j) {
        CP_WAIT1();          // stage j complete (j+1 may remain in flight)
        __syncthreads();     // CTA-wide visibility; all warps past compute j-1

        const int jn = j + STAGES - 1;
        if (jn < KITERS) {
            int sn = stage + 2;
            if (sn >= STAGES) sn -= STAGES;
            load_stage(sbase + sn * STAGE_BYTES, m0, n0, jn, tid);
        }
        CP_COMMIT();

        const uint32_t aBase = sbase + stage * STAGE_BYTES;
        const uint32_t bBase = aBase + A_BYTES;
        if (++stage == STAGES) stage = 0;

#pragma unroll
        for (int ks = 0; ks < 4; ++ks) {
            uint32_t af[2][4];
#pragma unroll
            for (int mt = 0; mt < 2; ++mt) {
                int row = mw * 32 + mt * 16 + a_rowsel;
                int chunk = ks * 2 + a_chunksel;
                uint32_t addr = aBase + row * 128 + ((chunk ^ (row & 7)) << 4);
                LDSM_X4(af[mt][0], af[mt][1], af[mt][2], af[mt][3], addr);
            }
            uint32_t bf[4][4];
#pragma unroll
            for (int g = 0; g < 4; ++g) {
                int row = nw * 64 + g * 16 + b_rowsel;
                int chunk = ks * 2 + b_chunksel;
                uint32_t addr = bBase + row * 128 + ((chunk ^ (row & 7)) << 4);
                LDSM_X4(bf[g][0], bf[g][1], bf[g][2], bf[g][3], addr);
            }
#pragma unroll
            for (int mt = 0; mt < 2; ++mt)
#pragma unroll
                for (int nt = 0; nt < 8; ++nt) {
                    const uint32_t b0 = bf[nt >> 1][(nt & 1) * 2 + 0];
                    const uint32_t b1 = bf[nt >> 1][(nt & 1) * 2 + 1];
                    MMA16816(acc[mt][nt], af[mt][0], af[mt][1], af[mt][2], af[mt][3], b0, b1);
                }
        }
    }

    // Epilogue: direct global stores + bias
    const int grp = lane >> 2, tig = lane & 3;
#pragma unroll
    for (int mt = 0; mt < 2; ++mt) {
        const int row0 = m0 + mw * 32 + mt * 16 + grp;
#pragma unroll
        for (int nt = 0; nt < 8; ++nt) {
            const int col = n0 + nw * 64 + nt * 8 + tig * 2;
            const float2 bb = *reinterpret_cast<const float2*>(bias + col);
            float2 v0, v1;
            v0.x = acc[mt][nt][0] + bb.x;
            v0.y = acc[mt][nt][1] + bb.y;
            v1.x = acc[mt][nt][2] + bb.x;
            v1.y = acc[mt][nt][3] + bb.y;
            *reinterpret_cast<float2*>(out + (size_t)row0 * NDIM + col) = v0;
            *reinterpret_cast<float2*>(out + (size_t)(row0 + 8) * NDIM + col) = v1;
        }
    }
}

// ---------------------------------------------------------------------------
// Launch
// ---------------------------------------------------------------------------
extern "C" void kernel_launch(void* const* d_in, const int* in_sizes, int n_in,
                              void* d_out, int out_size) {
    const float* x    = (const float*)d_in[0];   // [8192, 3072]
    const float* w    = (const float*)d_in[1];   // [3072, 1536]
    const float* b    = (const float*)d_in[2];   // [1536]
    const float* mask = (const float*)d_in[3];   // [1536, 3072]
    float* out = (float*)d_out;                  // [8192, 1536]

    // 1) x -> fp16
    conv_x_kernel<<<(MDIM * KDIM) / (256 * 8), 256>>>(x);

    // 2) Bh = fp16(mask * w^T)
    prep_B_kernel<<<dim3(KDIM / 32, NDIM / 32), dim3(32, 8)>>>(w, mask);

    // 3) fp16 HMMA GEMM, 2 CTAs/SM
    cudaFuncSetAttribute(gemm_f16_kernel, cudaFuncAttributeMaxDynamicSharedMemorySize,
                         SMEM_TOTAL);
    gemm_f16_kernel<<<TILES_M * TILES_N, 256, SMEM_TOTAL>>>(b, out);
}